// round 3
// baseline (speedup 1.0000x reference)
#include <cuda_runtime.h>
#include <cstdint>

// Problem constants (match reference_code)
constexpr int F     = 8;
constexpr int BL    = 4096 * 20;        // 81920 ids per feature
constexpr int DIM   = 128;              // floats per row
constexpr int VOCAB = 1000000;
constexpr long TOTAL_ROWS = (long)F * BL;   // 655360

// PERM from SPLIT_SIZES=(4,4), SPLIT_ORDER=(1,0) is [4,5,6,7,0,1,2,3]
// => f_in = f_out ^ 4.

constexpr int ROWS_PER_WARP = 4;
constexpr int THREADS = 256;            // 8 warps / block

__global__ __launch_bounds__(THREADS)
void embedding_gather_kernel(const int* __restrict__ vals,
                             const float* __restrict__ table,
                             float* __restrict__ out)
{
    const int lane   = threadIdx.x & 31;
    const long warp  = ((long)blockIdx.x * THREADS + threadIdx.x) >> 5;
    long row0 = warp * ROWS_PER_WARP;
    if (row0 >= TOTAL_ROWS) return;

    // Phase 1: fetch the (permuted) ids for up to ROWS_PER_WARP rows.
    unsigned slot[ROWS_PER_WARP];
    #pragma unroll
    for (int r = 0; r < ROWS_PER_WARP; r++) {
        long row = row0 + r;
        // guard tail (TOTAL_ROWS is a multiple of ROWS_PER_WARP here, but keep safe)
        long row_c = row < TOTAL_ROWS ? row : (TOTAL_ROWS - 1);
        int f_out = (int)(row_c / BL);
        int i     = (int)(row_c - (long)f_out * BL);
        int f_in  = f_out ^ 4;                       // feature-block permutation
        int v     = __ldg(&vals[(long)f_in * BL + i]);
        slot[r]   = (unsigned)v % (unsigned)VOCAB;   // hash-probe -> slot
    }

    // Phase 2: issue all row gathers back-to-back (maximize MLP),
    // then stream the stores.
    float4 buf[ROWS_PER_WARP];
    #pragma unroll
    for (int r = 0; r < ROWS_PER_WARP; r++) {
        const float4* src = reinterpret_cast<const float4*>(
            table + (size_t)slot[r] * DIM);
        buf[r] = __ldg(&src[lane]);
    }

    #pragma unroll
    for (int r = 0; r < ROWS_PER_WARP; r++) {
        long row = row0 + r;
        if (row < TOTAL_ROWS) {
            float4* dst = reinterpret_cast<float4*>(out + (size_t)row * DIM);
            __stcs(&dst[lane], buf[r]);   // streaming store: don't pollute L2
        }
    }
}

extern "C" void kernel_launch(void* const* d_in, const int* in_sizes, int n_in,
                              void* d_out, int out_size)
{
    const int*   vals  = (const int*)d_in[0];     // values: int32 [F, B*L]
    const float* table = (const float*)d_in[1];   // table: float32 [VOCAB, DIM]
    float*       out   = (float*)d_out;           // [F, B*L, DIM] float32

    const long total_warps = (TOTAL_ROWS + ROWS_PER_WARP - 1) / ROWS_PER_WARP;
    const long total_thr   = total_warps * 32;
    const int  blocks      = (int)((total_thr + THREADS - 1) / THREADS);

    embedding_gather_kernel<<<blocks, THREADS>>>(vals, table, out);
}